// round 4
// baseline (speedup 1.0000x reference)
#include <cuda_runtime.h>
#include <cstdint>

// s1, blur: [4, 10, 256, 256] fp32 -> out: [4, 256, 256] fp32.
//
// Round-3 finding: LDG path saturates at ~2.8 TB/s regardless of occupancy
// (per-SM L1tex/LSU outstanding-request ceiling on front-batched loads).
// This version streams through smem with cp.async.bulk (TMA path, mbarrier
// transaction tracking) which reaches the LTS chip cap (~6300 B/cyc)
// without consuming per-warp LDG slots.
//
// Each block: 512 contiguous pixels. 20 bulk copies (10 planes x {s1, blur},
// 2KB each) into 40KB static smem -> mbarrier wait -> 256 threads compute
// 2 pixels each from smem (stride-1, conflict-free).

#define NPLANES 10
#define HW      65536          // 256*256 (chunk never crosses a batch: 512 | 65536)
#define CHUNK   512
#define THREADS 256
#define TILE_BYTES (NPLANES * 2 * CHUNK * 4)   // 40960

__device__ __forceinline__ uint32_t smem_u32(const void* p) {
    return (uint32_t)__cvta_generic_to_shared(p);
}

__global__ __launch_bounds__(THREADS)
void distreg_kernel(const float* __restrict__ s1,
                    const float* __restrict__ blur,
                    float* __restrict__ out)
{
    __shared__ float    sm[2 * NPLANES][CHUNK];
    __shared__ uint64_t mbar;

    int tid = threadIdx.x;
    int p0  = blockIdx.x * CHUNK;       // first pixel of this block
    int b   = p0 >> 16;                 // batch
    int hw0 = p0 & (HW - 1);

    const float* s1p = s1   + (size_t)b * NPLANES * HW + hw0;
    const float* blp = blur + (size_t)b * NPLANES * HW + hw0;

    uint32_t mbar_a = smem_u32(&mbar);
    if (tid == 0) {
        asm volatile("mbarrier.init.shared.b64 [%0], 1;" :: "r"(mbar_a) : "memory");
    }
    __syncthreads();

    if (tid == 0) {
        asm volatile("mbarrier.arrive.expect_tx.shared.b64 _, [%0], %1;"
                     :: "r"(mbar_a), "r"((uint32_t)TILE_BYTES) : "memory");
        #pragma unroll
        for (int j = 0; j < NPLANES; j++) {
            asm volatile(
                "cp.async.bulk.shared::cluster.global.mbarrier::complete_tx::bytes "
                "[%0], [%1], %2, [%3];"
                :: "r"(smem_u32(&sm[j][0])), "l"(s1p + j * HW),
                   "r"((uint32_t)(CHUNK * 4)), "r"(mbar_a) : "memory");
            asm volatile(
                "cp.async.bulk.shared::cluster.global.mbarrier::complete_tx::bytes "
                "[%0], [%1], %2, [%3];"
                :: "r"(smem_u32(&sm[NPLANES + j][0])), "l"(blp + j * HW),
                   "r"((uint32_t)(CHUNK * 4)), "r"(mbar_a) : "memory");
        }
    }

    // All threads wait for the full 40KB tile (phase/parity 0).
    asm volatile(
        "{\n\t"
        ".reg .pred P;\n\t"
        "WAITLP_%=:\n\t"
        "mbarrier.try_wait.parity.acquire.cta.shared::cta.b64 P, [%0], 0, 0x989680;\n\t"
        "@P bra WAITDONE_%=;\n\t"
        "bra WAITLP_%=;\n\t"
        "WAITDONE_%=:\n\t"
        "}"
        :: "r"(mbar_a) : "memory");

    #pragma unroll
    for (int k = 0; k < CHUNK / THREADS; k++) {
        int idx = tid + k * THREADS;

        float svv[NPLANES], bvv[NPLANES];
        float sum = 0.f, sq = 0.f;
        #pragma unroll
        for (int j = 0; j < NPLANES; j++) {
            svv[j] = sm[j][idx];
            bvv[j] = sm[NPLANES + j][idx];
            float lo = svv[j] - bvv[j];
            sum += lo;
            sq   = fmaf(lo, lo, sq);
        }

        float bestM = 3.0e38f, bestSum = sum;
        #pragma unroll
        for (int i = 0; i <= NPLANES; i++) {
            float M = fmaf(-sum, sum * (1.0f / NPLANES), sq);  // sumsq - sum^2/n
            if (M < bestM) { bestM = M; bestSum = sum; }       // first index wins ties
            if (i < NPLANES) {
                sum = fmaf(2.0f, bvv[i], sum);
                sq  = fmaf(4.0f * svv[i], bvv[i], sq);
            }
        }
        out[p0 + idx] = bestSum * (1.0f / NPLANES);
    }
}

extern "C" void kernel_launch(void* const* d_in, const int* in_sizes, int n_in,
                              void* d_out, int out_size)
{
    const float* s1   = (const float*)d_in[0];
    const float* blur = (const float*)d_in[1];
    float* out = (float*)d_out;

    int blocks = out_size / CHUNK;     // 262144 / 512 = 512
    distreg_kernel<<<blocks, THREADS>>>(s1, blur, out);
}

// round 5
// speedup vs baseline: 1.2605x; 1.2605x over previous
#include <cuda_runtime.h>
#include <cuda_bf16.h>

// s1, blur: [4, 10, 256, 256] fp32 -> out: [4, 256, 256] fp32.
//
// Per pixel: candidate i (0..10): x_j = s_j + b_j for j<i else s_j - b_j.
// argmin_i std(x) , output mean of winner = sum_i / n.
//
// Scan identity: sumsq_i = (Σ lo_j^2) + Σ_{j<i} 4 s_j b_j ; the first term is
// common to all i, so argmin variance == argmin ( 4*P_i - sum_i^2/n ) with
// P_i = Σ_{j<i} s_j b_j , sum_i = (S - B) + Σ_{j<i} 2 b_j.
//
// float4 (LDG.128, best bytes/instr) + 512 CTAs x 128 threads for smooth
// per-SM balance (round-2's 256-CTA grid had a 2:1 CTA imbalance tail).

#define NPLANES 10
#define HW4     16384   // (256*256)/4 quads per plane

__global__ __launch_bounds__(128)
void distregression_kernel(const float4* __restrict__ s1,
                           const float4* __restrict__ blur,
                           float4* __restrict__ out,
                           int nquads)
{
    int t = blockIdx.x * blockDim.x + threadIdx.x;
    if (t >= nquads) return;

    int b   = t >> 14;            // quad / HW4 -> batch
    int hw4 = t & (HW4 - 1);

    const float4* s1p = s1   + (size_t)b * NPLANES * HW4 + hw4;
    const float4* blp = blur + (size_t)b * NPLANES * HW4 + hw4;

    // Front-batch all 20 LDG.128 (max MLP).
    float sv[NPLANES][4], bv[NPLANES][4];
    #pragma unroll
    for (int j = 0; j < NPLANES; j++) {
        float4 s = __ldg(s1p + j * HW4);
        float4 v = __ldg(blp + j * HW4);
        sv[j][0] = s.x; sv[j][1] = s.y; sv[j][2] = s.z; sv[j][3] = s.w;
        bv[j][0] = v.x; bv[j][1] = v.y; bv[j][2] = v.z; bv[j][3] = v.w;
    }

    const float inv_n = 1.0f / NPLANES;
    float res[4];
    #pragma unroll
    for (int k = 0; k < 4; k++) {
        float S = 0.f, B = 0.f;
        #pragma unroll
        for (int j = 0; j < NPLANES; j++) {
            S += sv[j][k];
            B += bv[j][k];
        }

        float sum = S - B;     // candidate 0: all lo
        float P   = 0.f;       // Σ_{j<i} s_j b_j
        float bestM = 3.0e38f, bestSum = sum;

        #pragma unroll
        for (int i = 0; i <= NPLANES; i++) {
            float M = fmaf(-sum * inv_n, sum, 4.0f * P);
            if (M < bestM) { bestM = M; bestSum = sum; }   // first index wins ties
            if (i < NPLANES) {
                sum = fmaf(2.0f, bv[i][k], sum);
                P   = fmaf(sv[i][k], bv[i][k], P);
            }
        }
        res[k] = bestSum * inv_n;
    }

    out[t] = make_float4(res[0], res[1], res[2], res[3]);
}

extern "C" void kernel_launch(void* const* d_in, const int* in_sizes, int n_in,
                              void* d_out, int out_size)
{
    const float4* s1   = (const float4*)d_in[0];
    const float4* blur = (const float4*)d_in[1];
    float4* out = (float4*)d_out;

    int nquads  = out_size / 4;          // 65536
    int threads = 128;
    int blocks  = (nquads + threads - 1) / threads;   // 512
    distregression_kernel<<<blocks, threads>>>(s1, blur, out, nquads);
}

// round 6
// speedup vs baseline: 1.3029x; 1.0337x over previous
#include <cuda_runtime.h>
#include <cuda_bf16.h>

// s1, blur: [4, 10, 256, 256] fp32 -> out: [4, 256, 256] fp32.
//
// Per pixel: candidate i (0..10): x_j = s_j + b_j for j<i else s_j - b_j.
// argmin_i std(x); output mean of winner = sum_i / n.
// Identity: argmin variance == argmin ( 4*P_i - sum_i^2/n ),
//   P_i = prefix Σ s_j b_j, sum_i = (S - B) + 2 * prefix Σ b_j.
//
// Round-5 diagnosis: DRAM only ~33% duty because load phases of the few
// resident warps don't tile the timeline (one-shot wave, low occupancy).
// This version: scalar 1 pixel/thread (~40 regs) -> 40+ warps/SM resident,
// 2-3x more concurrent load phases. Same total DRAM line traffic.

#define NPLANES 10
#define HW      65536   // 256*256

__global__ __launch_bounds__(256, 5)
void distregression_kernel(const float* __restrict__ s1,
                           const float* __restrict__ blur,
                           float* __restrict__ out,
                           int npix)
{
    int pix = blockIdx.x * blockDim.x + threadIdx.x;
    if (pix >= npix) return;

    int b  = pix >> 16;           // batch
    int hw = pix & (HW - 1);

    const float* s1p = s1   + (size_t)b * NPLANES * HW + hw;
    const float* blp = blur + (size_t)b * NPLANES * HW + hw;

    // Front-batch all 20 coalesced scalar loads (MLP=20 per thread).
    float sv[NPLANES], bv[NPLANES];
    #pragma unroll
    for (int j = 0; j < NPLANES; j++) {
        sv[j] = __ldg(s1p + j * HW);
        bv[j] = __ldg(blp + j * HW);
    }

    float S = 0.f, B = 0.f;
    #pragma unroll
    for (int j = 0; j < NPLANES; j++) {
        S += sv[j];
        B += bv[j];
    }

    const float inv_n = 1.0f / NPLANES;
    float sum = S - B;    // candidate 0: all lo
    float P   = 0.f;      // prefix Σ s_j b_j
    float bestM = 3.0e38f, bestSum = sum;

    #pragma unroll
    for (int i = 0; i <= NPLANES; i++) {
        float M = fmaf(-sum * inv_n, sum, 4.0f * P);
        if (M < bestM) { bestM = M; bestSum = sum; }   // first index wins ties
        if (i < NPLANES) {
            sum = fmaf(2.0f, bv[i], sum);
            P   = fmaf(sv[i], bv[i], P);
        }
    }

    out[pix] = bestSum * inv_n;
}

extern "C" void kernel_launch(void* const* d_in, const int* in_sizes, int n_in,
                              void* d_out, int out_size)
{
    const float* s1   = (const float*)d_in[0];
    const float* blur = (const float*)d_in[1];
    float* out = (float*)d_out;

    int npix    = out_size;                    // 262144
    int threads = 256;
    int blocks  = (npix + threads - 1) / threads;   // 1024
    distregression_kernel<<<blocks, threads>>>(s1, blur, out, npix);
}